// round 1
// baseline (speedup 1.0000x reference)
#include <cuda_runtime.h>
#include <cuda_bf16.h>
#include <cstdint>

// Problem constants
#define B_   4
#define T_   4096
#define D_   1024
#define E_   1024
#define TWOE 2048
#define BT   (B_ * T_)          // 16384 rows
#define EPS_ 1e-8f

// Scratch (no allocations allowed -> __device__ globals)
__device__ float g_z1[(size_t)BT * TWOE];    // pre-norm in_proj output  (128 MiB)
__device__ float g_s1[BT];                   // per-row rsqrt scale
__device__ float g_gated[(size_t)BT * E_];   // gated conv output        (64 MiB)

// ---------------------------------------------------------------------------
// GEMM (NT): C[m,n] = sum_k A[m,k] * B[n,k] + bias[n]
// A: [M,K] row-major, B: [N,K] row-major. M%128==0, N%128==0, K%16==0.
// 128x128 tile, BK=16, 256 threads, 8x8 per-thread microtile.
// ---------------------------------------------------------------------------
#define BM 128
#define BN 128
#define BK 16
#define SPAD 4   // smem row stride = 132 floats (16B-aligned, kills STS conflicts)

__global__ __launch_bounds__(256, 2)
void gemm_nt_bias(const float* __restrict__ A, const float* __restrict__ Bm,
                  const float* __restrict__ bias, float* __restrict__ C,
                  int M, int N, int K)
{
    __shared__ float As[BK][BM + SPAD];
    __shared__ float Bs[BK][BN + SPAD];

    const int tid = threadIdx.x;           // 0..255
    const int bm = blockIdx.y * BM;
    const int bn = blockIdx.x * BN;
    const int ty = tid >> 4;               // 0..15
    const int tx = tid & 15;               // 0..15

    float acc[8][8];
    #pragma unroll
    for (int i = 0; i < 8; ++i)
        #pragma unroll
        for (int j = 0; j < 8; ++j) acc[i][j] = 0.f;

    for (int k0 = 0; k0 < K; k0 += BK) {
        // Load A tile (128 rows x 16 cols) and B tile: 512 float4 each, 2/thread
        #pragma unroll
        for (int it = 0; it < 2; ++it) {
            int id  = tid + it * 256;      // 0..511
            int row = id >> 2;             // 0..127
            int c4  = (id & 3) << 2;       // 0,4,8,12
            float4 av = *(const float4*)&A [(size_t)(bm + row) * K + k0 + c4];
            As[c4 + 0][row] = av.x; As[c4 + 1][row] = av.y;
            As[c4 + 2][row] = av.z; As[c4 + 3][row] = av.w;
            float4 bv = *(const float4*)&Bm[(size_t)(bn + row) * K + k0 + c4];
            Bs[c4 + 0][row] = bv.x; Bs[c4 + 1][row] = bv.y;
            Bs[c4 + 2][row] = bv.z; Bs[c4 + 3][row] = bv.w;
        }
        __syncthreads();

        #pragma unroll
        for (int k = 0; k < BK; ++k) {
            float a[8], b[8];
            float4 a0 = *(const float4*)&As[k][ty * 8];
            float4 a1 = *(const float4*)&As[k][ty * 8 + 4];
            float4 b0 = *(const float4*)&Bs[k][tx * 8];
            float4 b1 = *(const float4*)&Bs[k][tx * 8 + 4];
            a[0]=a0.x; a[1]=a0.y; a[2]=a0.z; a[3]=a0.w;
            a[4]=a1.x; a[5]=a1.y; a[6]=a1.z; a[7]=a1.w;
            b[0]=b0.x; b[1]=b0.y; b[2]=b0.z; b[3]=b0.w;
            b[4]=b1.x; b[5]=b1.y; b[6]=b1.z; b[7]=b1.w;
            #pragma unroll
            for (int i = 0; i < 8; ++i)
                #pragma unroll
                for (int j = 0; j < 8; ++j)
                    acc[i][j] = fmaf(a[i], b[j], acc[i][j]);
        }
        __syncthreads();
    }

    // Epilogue: add bias, vectorized stores
    const int cb = bn + tx * 8;
    float4 bias0 = *(const float4*)&bias[cb];
    float4 bias1 = *(const float4*)&bias[cb + 4];
    #pragma unroll
    for (int i = 0; i < 8; ++i) {
        int r = bm + ty * 8 + i;
        float4 v0, v1;
        v0.x = acc[i][0] + bias0.x; v0.y = acc[i][1] + bias0.y;
        v0.z = acc[i][2] + bias0.z; v0.w = acc[i][3] + bias0.w;
        v1.x = acc[i][4] + bias1.x; v1.y = acc[i][5] + bias1.y;
        v1.z = acc[i][6] + bias1.z; v1.w = acc[i][7] + bias1.w;
        *(float4*)&C[(size_t)r * N + cb]     = v0;
        *(float4*)&C[(size_t)r * N + cb + 4] = v1;
    }
}

// ---------------------------------------------------------------------------
// Per-row RMS scale over 2048 cols of g_z1: s1[row] = rsqrt(mean(z^2)+eps)
// ---------------------------------------------------------------------------
__global__ void row_rms_scale(const float* __restrict__ z, float* __restrict__ s)
{
    const int row = blockIdx.x;
    const float4* p = (const float4*)(z + (size_t)row * TWOE);
    float acc = 0.f;
    // 2048 floats = 512 float4, 256 threads -> 2 each
    #pragma unroll
    for (int it = 0; it < 2; ++it) {
        float4 v = p[threadIdx.x + it * 256];
        acc += v.x*v.x + v.y*v.y + v.z*v.z + v.w*v.w;
    }
    // reduce
    #pragma unroll
    for (int o = 16; o > 0; o >>= 1) acc += __shfl_xor_sync(0xffffffff, acc, o);
    __shared__ float warpsum[8];
    if ((threadIdx.x & 31) == 0) warpsum[threadIdx.x >> 5] = acc;
    __syncthreads();
    if (threadIdx.x == 0) {
        float t = 0.f;
        #pragma unroll
        for (int w = 0; w < 8; ++w) t += warpsum[w];
        s[row] = rsqrtf(t * (1.0f / TWOE) + EPS_);
    }
}

// ---------------------------------------------------------------------------
// Depthwise conv (K=3, 'same', cross-correlation) + gate.
// xn(b,tau,e) = z1[row(tau), e] * s1[row(tau)] * in_norm_w[e]
// vn(b,t,e)   = z1[row(t), E+e] * s1[row(t)]  * in_norm_w[E+e]
// gated = vn * (conv_b[e] + sum_k conv_w[e,k] * xn(b, t+k-1, e))
// ---------------------------------------------------------------------------
__global__ void conv_gate(const float* __restrict__ z1, const float* __restrict__ s1,
                          const float* __restrict__ innw,
                          const float* __restrict__ cw, const float* __restrict__ cb,
                          float* __restrict__ gated)
{
    const int idx = blockIdx.x * blockDim.x + threadIdx.x;   // over BT*E
    const int e   = idx & (E_ - 1);
    const int row = idx >> 10;
    const int t   = row & (T_ - 1);

    const float wn  = innw[e];
    const float wnv = innw[E_ + e];
    const float w0 = cw[e * 3 + 0], w1 = cw[e * 3 + 1], w2 = cw[e * 3 + 2];

    const float sc = s1[row];
    float xm = cb[e];
    if (t > 0) {
        xm = fmaf(w0, z1[(size_t)(row - 1) * TWOE + e] * s1[row - 1] * wn, xm);
    }
    xm = fmaf(w1, z1[(size_t)row * TWOE + e] * sc * wn, xm);
    if (t < T_ - 1) {
        xm = fmaf(w2, z1[(size_t)(row + 1) * TWOE + e] * s1[row + 1] * wn, xm);
    }
    const float v = z1[(size_t)row * TWOE + E_ + e] * sc * wnv;
    gated[idx] = v * xm;
}

// ---------------------------------------------------------------------------
// In-place row RMSNorm over 1024 cols of out (post out_proj), apply out_norm_w
// ---------------------------------------------------------------------------
__global__ void out_rmsnorm(float* __restrict__ out, const float* __restrict__ w)
{
    const int row = blockIdx.x;
    float4* p = (float4*)(out + (size_t)row * D_);
    float4 v = p[threadIdx.x];                  // 256 threads x 4 = 1024
    float acc = v.x*v.x + v.y*v.y + v.z*v.z + v.w*v.w;
    #pragma unroll
    for (int o = 16; o > 0; o >>= 1) acc += __shfl_xor_sync(0xffffffff, acc, o);
    __shared__ float warpsum[8];
    __shared__ float s_bcast;
    if ((threadIdx.x & 31) == 0) warpsum[threadIdx.x >> 5] = acc;
    __syncthreads();
    if (threadIdx.x == 0) {
        float tsum = 0.f;
        #pragma unroll
        for (int wi = 0; wi < 8; ++wi) tsum += warpsum[wi];
        s_bcast = rsqrtf(tsum * (1.0f / D_) + EPS_);
    }
    __syncthreads();
    const float s = s_bcast;
    float4 wv = *(const float4*)&w[threadIdx.x * 4];
    v.x *= s * wv.x; v.y *= s * wv.y; v.z *= s * wv.z; v.w *= s * wv.w;
    p[threadIdx.x] = v;
}

// ---------------------------------------------------------------------------
// Launch
// Inputs (metadata order): u, W_in, b_in, in_norm_w, conv_w, conv_b,
//                          W_out, b_out, out_norm_w
// ---------------------------------------------------------------------------
extern "C" void kernel_launch(void* const* d_in, const int* in_sizes, int n_in,
                              void* d_out, int out_size)
{
    const float* u      = (const float*)d_in[0];
    const float* W_in   = (const float*)d_in[1];
    const float* b_in   = (const float*)d_in[2];
    const float* innw   = (const float*)d_in[3];
    const float* conv_w = (const float*)d_in[4];
    const float* conv_b = (const float*)d_in[5];
    const float* W_out  = (const float*)d_in[6];
    const float* b_out  = (const float*)d_in[7];
    const float* outnw  = (const float*)d_in[8];
    float* out = (float*)d_out;

    float *z1, *s1, *gated;
    cudaGetSymbolAddress((void**)&z1,    g_z1);
    cudaGetSymbolAddress((void**)&s1,    g_s1);
    cudaGetSymbolAddress((void**)&gated, g_gated);

    // 1) in_proj GEMM + bias  -> z1 [BT, 2048]
    {
        dim3 grid(TWOE / BN, BT / BM);
        gemm_nt_bias<<<grid, 256>>>(u, W_in, b_in, z1, BT, TWOE, D_);
    }
    // 2) per-row RMS scale over 2048
    row_rms_scale<<<BT, 256>>>(z1, s1);
    // 3) conv + gate -> gated [BT, 1024]
    conv_gate<<<(BT * E_) / 256, 256>>>(z1, s1, innw, conv_w, conv_b, gated);
    // 4) out_proj GEMM + bias -> out (raw)
    {
        dim3 grid(D_ / BN, BT / BM);
        gemm_nt_bias<<<grid, 256>>>(gated, W_out, b_out, out, BT, D_, E_);
    }
    // 5) in-place RMSNorm on out rows
    out_rmsnorm<<<BT, 256>>>(out, outnw);
}

// round 3
// speedup vs baseline: 2.2116x; 2.2116x over previous
#include <cuda_runtime.h>
#include <cuda_bf16.h>
#include <cstdint>

// ---------------------------------------------------------------------------
// Problem constants
// ---------------------------------------------------------------------------
#define B_   4
#define T_   4096
#define D_   1024
#define E_   1024
#define TWOE 2048
#define BT   (B_ * T_)          // 16384 rows
#define EPS_ 1e-8f

// ---------------------------------------------------------------------------
// Scratch (__device__ globals; no runtime allocation allowed)
// ---------------------------------------------------------------------------
__device__ float         g_z1[(size_t)BT * TWOE];     // in_proj pre-norm (fp32)
__device__ float         g_s1[BT];                    // row rsqrt scale
__device__ __nv_bfloat16 g_uhi[(size_t)BT * D_];
__device__ __nv_bfloat16 g_ulo[(size_t)BT * D_];
__device__ __nv_bfloat16 g_w1hi[(size_t)TWOE * D_];
__device__ __nv_bfloat16 g_w1lo[(size_t)TWOE * D_];
__device__ __nv_bfloat16 g_ghi[(size_t)BT * E_];
__device__ __nv_bfloat16 g_glo[(size_t)BT * E_];
__device__ __nv_bfloat16 g_w2hi[(size_t)D_ * E_];
__device__ __nv_bfloat16 g_w2lo[(size_t)D_ * E_];

// ---------------------------------------------------------------------------
// HMMA split-bf16 GEMM (NT): C[m,n] = sum_k A[m,k]*B[n,k] + bias[n]
//   C = Ahi*Bhi + Ahi*Blo + Alo*Bhi   (fp32 accum; lo*lo dropped)
// 128x128 CTA tile, BK=16, 8 warps -> warp tile 64x32, m16n8k16 frags.
// 2-stage cp.async double buffer, 48KB static smem, 48B row stride
// (granule (3*row + chunk) % 8 is a permutation -> conflict-free ldmatrix).
// ---------------------------------------------------------------------------
#define GM 128
#define GN 128
#define GK 16
#define ROWB 48                   // bytes per smem row (16 bf16 = 32B data + pad)
#define TILEB (128 * ROWB)        // 6144 B per tile
// tile order within a stage: Ahi, Alo, Bhi, Blo
#define STAGEB (4 * TILEB)        // 24576 B

__device__ __forceinline__ uint32_t smem_u32(const void* p) {
    uint32_t a;
    asm("{ .reg .u64 t; cvta.to.shared.u64 t, %1; cvt.u32.u64 %0, t; }" : "=r"(a) : "l"(p));
    return a;
}
__device__ __forceinline__ void cp_async16(uint32_t dst, const void* src) {
    asm volatile("cp.async.cg.shared.global [%0], [%1], 16;\n" :: "r"(dst), "l"(src));
}
__device__ __forceinline__ void cp_commit() { asm volatile("cp.async.commit_group;\n"); }
__device__ __forceinline__ void cp_wait_all() { asm volatile("cp.async.wait_group 0;\n"); }

__device__ __forceinline__ void ldmat_x4(uint32_t* r, uint32_t addr) {
    asm volatile("ldmatrix.sync.aligned.m8n8.x4.shared.b16 {%0,%1,%2,%3}, [%4];"
                 : "=r"(r[0]), "=r"(r[1]), "=r"(r[2]), "=r"(r[3]) : "r"(addr));
}
__device__ __forceinline__ void mma_bf16(float* d, const uint32_t* a, const uint32_t* b) {
    asm volatile(
        "mma.sync.aligned.m16n8k16.row.col.f32.bf16.bf16.f32 "
        "{%0,%1,%2,%3}, {%4,%5,%6,%7}, {%8,%9}, {%0,%1,%2,%3};"
        : "+f"(d[0]), "+f"(d[1]), "+f"(d[2]), "+f"(d[3])
        : "r"(a[0]), "r"(a[1]), "r"(a[2]), "r"(a[3]), "r"(b[0]), "r"(b[1]));
}

__global__ __launch_bounds__(256, 1)
void gemm_hmma_bf16x2(const __nv_bfloat16* __restrict__ Ahi, const __nv_bfloat16* __restrict__ Alo,
                      const __nv_bfloat16* __restrict__ Bhi, const __nv_bfloat16* __restrict__ Blo,
                      const float* __restrict__ bias, float* __restrict__ C,
                      int M, int N, int K)
{
    __shared__ char smem[2 * STAGEB];          // 48 KB
    const uint32_t sbase = smem_u32(smem);
    const int tid  = threadIdx.x;
    const int wid  = tid >> 5;
    const int lane = tid & 31;
    const int bm = blockIdx.y * GM;
    const int bn = blockIdx.x * GN;
    const int wm = (wid >> 2) * 64;            // 0 / 64
    const int wn = (wid & 3) * 32;             // 0 / 32 / 64 / 96

    // stage loader: 4 tiles x 128 rows x 2 chunks(16B) = 1024 cp.async / 256 thr
    auto load_stage = [&](int stage, int k0) {
        const uint32_t dst0 = sbase + stage * STAGEB;
        #pragma unroll
        for (int i = 0; i < 4; ++i) {
            int id  = tid + i * 256;           // 0..1023
            int t   = id >> 8;                 // tile 0..3
            int w   = id & 255;
            int row = w >> 1;
            int c   = w & 1;
            const __nv_bfloat16* src;
            if      (t == 0) src = Ahi + (size_t)(bm + row) * K + k0 + c * 8;
            else if (t == 1) src = Alo + (size_t)(bm + row) * K + k0 + c * 8;
            else if (t == 2) src = Bhi + (size_t)(bn + row) * K + k0 + c * 8;
            else             src = Blo + (size_t)(bn + row) * K + k0 + c * 8;
            cp_async16(dst0 + t * TILEB + row * ROWB + c * 16, src);
        }
        cp_commit();
    };

    float acc[4][4][4];
    #pragma unroll
    for (int i = 0; i < 4; ++i)
        #pragma unroll
        for (int j = 0; j < 4; ++j)
            #pragma unroll
            for (int q = 0; q < 4; ++q) acc[i][j][q] = 0.f;

    const int chunks = K / GK;
    load_stage(0, 0);

    // lane->address decode for ldmatrix
    const int l8  = lane & 7;
    const int sel = lane >> 3;                 // 0..3
    const int a_row = (sel & 1) * 8 + l8;      // A: matrices (r0-7,c0),(r8-15,c0),(r0-7,c1),(r8-15,c1)
    const int a_c   = sel >> 1;
    const int b_row = (sel >> 1) * 8 + l8;     // B: matrices (n0-7,c0),(n0-7,c1),(n8-15,c0),(n8-15,c1)
    const int b_c   = sel & 1;

    for (int ch = 0; ch < chunks; ++ch) {
        cp_wait_all();
        __syncthreads();
        if (ch + 1 < chunks) load_stage((ch + 1) & 1, (ch + 1) * GK);

        const uint32_t st = sbase + (ch & 1) * STAGEB;
        const uint32_t aHiB = st + 0 * TILEB;
        const uint32_t aLoB = st + 1 * TILEB;
        const uint32_t bHiB = st + 2 * TILEB;
        const uint32_t bLoB = st + 3 * TILEB;

        uint32_t ahi[4][4], alo[4][4], bhi[4][2], blo[4][2];
        #pragma unroll
        for (int mi = 0; mi < 4; ++mi) {
            uint32_t ra = (uint32_t)((wm + mi * 16 + a_row) * ROWB + a_c * 16);
            ldmat_x4(ahi[mi], aHiB + ra);
            ldmat_x4(alo[mi], aLoB + ra);
        }
        #pragma unroll
        for (int jp = 0; jp < 2; ++jp) {
            uint32_t rb = (uint32_t)((wn + jp * 16 + b_row) * ROWB + b_c * 16);
            uint32_t th[4], tl[4];
            ldmat_x4(th, bHiB + rb);
            ldmat_x4(tl, bLoB + rb);
            bhi[jp*2  ][0] = th[0]; bhi[jp*2  ][1] = th[1];
            bhi[jp*2+1][0] = th[2]; bhi[jp*2+1][1] = th[3];
            blo[jp*2  ][0] = tl[0]; blo[jp*2  ][1] = tl[1];
            blo[jp*2+1][0] = tl[2]; blo[jp*2+1][1] = tl[3];
        }

        #pragma unroll
        for (int mi = 0; mi < 4; ++mi)
            #pragma unroll
            for (int nj = 0; nj < 4; ++nj) {
                mma_bf16(acc[mi][nj], ahi[mi], bhi[nj]);
                mma_bf16(acc[mi][nj], ahi[mi], blo[nj]);
                mma_bf16(acc[mi][nj], alo[mi], bhi[nj]);
            }
        __syncthreads();
    }

    // epilogue: frag layout row = lane/4 (+8), col = 2*(lane%4) (+1)
    const int er = lane >> 2;
    const int ec = (lane & 3) * 2;
    #pragma unroll
    for (int mi = 0; mi < 4; ++mi) {
        #pragma unroll
        for (int nj = 0; nj < 4; ++nj) {
            int row0 = bm + wm + mi * 16 + er;
            int col  = bn + wn + nj * 8 + ec;
            float b0 = bias[col], b1 = bias[col + 1];
            float2 v0 = make_float2(acc[mi][nj][0] + b0, acc[mi][nj][1] + b1);
            float2 v1 = make_float2(acc[mi][nj][2] + b0, acc[mi][nj][3] + b1);
            *(float2*)&C[(size_t)row0 * N + col]       = v0;
            *(float2*)&C[(size_t)(row0 + 8) * N + col] = v1;
        }
    }
}

// ---------------------------------------------------------------------------
// Elementwise kernels
// ---------------------------------------------------------------------------
// split fp32 -> bf16 hi/lo (4 elems per thread)
__global__ void split_bf16(const float* __restrict__ x,
                           __nv_bfloat16* __restrict__ hi, __nv_bfloat16* __restrict__ lo,
                           int n4)
{
    int i = blockIdx.x * blockDim.x + threadIdx.x;
    if (i >= n4) return;
    float4 v = ((const float4*)x)[i];
    __nv_bfloat16 h[4], l[4];
    float f[4] = {v.x, v.y, v.z, v.w};
    #pragma unroll
    for (int j = 0; j < 4; ++j) {
        h[j] = __float2bfloat16(f[j]);
        l[j] = __float2bfloat16(f[j] - __bfloat162float(h[j]));
    }
    ((uint2*)hi)[i] = *(uint2*)h;
    ((uint2*)lo)[i] = *(uint2*)l;
}

// per-row rsqrt(mean(z^2)+eps) over 2048 cols
__global__ void row_rms_scale(const float* __restrict__ z, float* __restrict__ s)
{
    const int row = blockIdx.x;
    const float4* p = (const float4*)(z + (size_t)row * TWOE);
    float acc = 0.f;
    #pragma unroll
    for (int it = 0; it < 2; ++it) {
        float4 v = p[threadIdx.x + it * 256];
        acc += v.x*v.x + v.y*v.y + v.z*v.z + v.w*v.w;
    }
    #pragma unroll
    for (int o = 16; o > 0; o >>= 1) acc += __shfl_xor_sync(0xffffffff, acc, o);
    __shared__ float warpsum[8];
    if ((threadIdx.x & 31) == 0) warpsum[threadIdx.x >> 5] = acc;
    __syncthreads();
    if (threadIdx.x == 0) {
        float t = 0.f;
        #pragma unroll
        for (int w = 0; w < 8; ++w) t += warpsum[w];
        s[row] = rsqrtf(t * (1.0f / TWOE) + EPS_);
    }
}

// conv(K=3,'same') + gate; writes gated as bf16 hi/lo
__global__ void conv_gate(const float* __restrict__ z1, const float* __restrict__ s1,
                          const float* __restrict__ innw,
                          const float* __restrict__ cw, const float* __restrict__ cb,
                          __nv_bfloat16* __restrict__ ghi, __nv_bfloat16* __restrict__ glo)
{
    const int idx = blockIdx.x * blockDim.x + threadIdx.x;   // over BT*E
    const int e   = idx & (E_ - 1);
    const int row = idx >> 10;
    const int t   = row & (T_ - 1);

    const float wn  = innw[e];
    const float wnv = innw[E_ + e];
    const float w0 = cw[e * 3 + 0], w1 = cw[e * 3 + 1], w2 = cw[e * 3 + 2];

    const float sc = s1[row];
    float xm = cb[e];
    if (t > 0)
        xm = fmaf(w0, z1[(size_t)(row - 1) * TWOE + e] * s1[row - 1] * wn, xm);
    xm = fmaf(w1, z1[(size_t)row * TWOE + e] * sc * wn, xm);
    if (t < T_ - 1)
        xm = fmaf(w2, z1[(size_t)(row + 1) * TWOE + e] * s1[row + 1] * wn, xm);
    const float v = z1[(size_t)row * TWOE + E_ + e] * sc * wnv;
    const float g = v * xm;
    __nv_bfloat16 h = __float2bfloat16(g);
    ghi[idx] = h;
    glo[idx] = __float2bfloat16(g - __bfloat162float(h));
}

// in-place row RMSNorm over 1024 cols
__global__ void out_rmsnorm(float* __restrict__ out, const float* __restrict__ w)
{
    const int row = blockIdx.x;
    float4* p = (float4*)(out + (size_t)row * D_);
    float4 v = p[threadIdx.x];                  // 256 x 4 = 1024
    float acc = v.x*v.x + v.y*v.y + v.z*v.z + v.w*v.w;
    #pragma unroll
    for (int o = 16; o > 0; o >>= 1) acc += __shfl_xor_sync(0xffffffff, acc, o);
    __shared__ float warpsum[8];
    __shared__ float s_bcast;
    if ((threadIdx.x & 31) == 0) warpsum[threadIdx.x >> 5] = acc;
    __syncthreads();
    if (threadIdx.x == 0) {
        float tsum = 0.f;
        #pragma unroll
        for (int wi = 0; wi < 8; ++wi) tsum += warpsum[wi];
        s_bcast = rsqrtf(tsum * (1.0f / D_) + EPS_);
    }
    __syncthreads();
    const float s = s_bcast;
    float4 wv = *(const float4*)&w[threadIdx.x * 4];
    v.x *= s * wv.x; v.y *= s * wv.y; v.z *= s * wv.z; v.w *= s * wv.w;
    p[threadIdx.x] = v;
}

// ---------------------------------------------------------------------------
// Launch
// Inputs (metadata order): u, W_in, b_in, in_norm_w, conv_w, conv_b,
//                          W_out, b_out, out_norm_w
// ---------------------------------------------------------------------------
extern "C" void kernel_launch(void* const* d_in, const int* in_sizes, int n_in,
                              void* d_out, int out_size)
{
    const float* u      = (const float*)d_in[0];
    const float* W_in   = (const float*)d_in[1];
    const float* b_in   = (const float*)d_in[2];
    const float* innw   = (const float*)d_in[3];
    const float* conv_w = (const float*)d_in[4];
    const float* conv_b = (const float*)d_in[5];
    const float* W_out  = (const float*)d_in[6];
    const float* b_out  = (const float*)d_in[7];
    const float* outnw  = (const float*)d_in[8];
    float* out = (float*)d_out;

    float *z1, *s1;
    __nv_bfloat16 *uhi, *ulo, *w1hi, *w1lo, *ghi, *glo, *w2hi, *w2lo;
    cudaGetSymbolAddress((void**)&z1,   g_z1);
    cudaGetSymbolAddress((void**)&s1,   g_s1);
    cudaGetSymbolAddress((void**)&uhi,  g_uhi);
    cudaGetSymbolAddress((void**)&ulo,  g_ulo);
    cudaGetSymbolAddress((void**)&w1hi, g_w1hi);
    cudaGetSymbolAddress((void**)&w1lo, g_w1lo);
    cudaGetSymbolAddress((void**)&ghi,  g_ghi);
    cudaGetSymbolAddress((void**)&glo,  g_glo);
    cudaGetSymbolAddress((void**)&w2hi, g_w2hi);
    cudaGetSymbolAddress((void**)&w2lo, g_w2lo);

    // 1) split inputs/weights to bf16 hi/lo
    split_bf16<<<((BT * D_ / 4) + 255) / 256, 256>>>(u,     uhi,  ulo,  BT * D_ / 4);
    split_bf16<<<((TWOE * D_ / 4) + 255) / 256, 256>>>(W_in, w1hi, w1lo, TWOE * D_ / 4);
    split_bf16<<<((D_ * E_ / 4) + 255) / 256, 256>>>(W_out, w2hi, w2lo, D_ * E_ / 4);

    // 2) in_proj GEMM (HMMA) + bias -> z1
    {
        dim3 grid(TWOE / GN, BT / GM);
        gemm_hmma_bf16x2<<<grid, 256>>>(uhi, ulo, w1hi, w1lo, b_in, z1, BT, TWOE, D_);
    }
    // 3) row scale
    row_rms_scale<<<BT, 256>>>(z1, s1);

    // 4) conv + gate -> gated bf16 hi/lo
    conv_gate<<<(BT * E_) / 256, 256>>>(z1, s1, innw, conv_w, conv_b, ghi, glo);

    // 5) out_proj GEMM + bias -> out (raw)
    {
        dim3 grid(D_ / GN, BT / GM);
        gemm_hmma_bf16x2<<<grid, 256>>>(ghi, glo, w2hi, w2lo, b_out, out, BT, D_, E_);
    }
    // 6) in-place RMSNorm on out rows
    out_rmsnorm<<<BT, 256>>>(out, outnw);
}